// round 2
// baseline (speedup 1.0000x reference)
#include <cuda_runtime.h>

#define HH   512
#define WW   512
#define HWSZ (HH * WW)
#define CIN  32
#define COUT 24
#define NP   8

typedef unsigned long long u64;

// ---- B300 packed-f32 helpers (PTX f32x2 ops -> FFMA2 in SASS) ----
__device__ __forceinline__ u64 fma2_(u64 a, u64 b, u64 c) {
    u64 d; asm("fma.rn.f32x2 %0, %1, %2, %3;" : "=l"(d) : "l"(a), "l"(b), "l"(c)); return d;
}
__device__ __forceinline__ u64 add2_(u64 a, u64 b) {
    u64 d; asm("add.rn.f32x2 %0, %1, %2;" : "=l"(d) : "l"(a), "l"(b)); return d;
}
__device__ __forceinline__ u64 mul2_(u64 a, u64 b) {
    u64 d; asm("mul.rn.f32x2 %0, %1, %2;" : "=l"(d) : "l"(a), "l"(b)); return d;
}
__device__ __forceinline__ u64 pack2_(float lo, float hi) {
    u64 r; asm("mov.b64 %0, {%1, %2};" : "=l"(r) : "f"(lo), "f"(hi)); return r;
}
__device__ __forceinline__ float2 unpack2_(u64 v) {
    float lo, hi; asm("mov.b64 {%0, %1}, %2;" : "=f"(lo), "=f"(hi) : "l"(v));
    return make_float2(lo, hi);
}

// Thread = 4 x-adjacent pixels (x0 % 4 == 0). The 12-float tap window
// [x0-4, x0+7] is assembled from the thread's OWN 16B load plus neighbor
// lanes' loads via warp shuffle (lanes 0/31 patch the halo with one
// predicated LDG). Phase 1 builds 25 pre-normalized weights (100 floats in
// regs); phase 2 streams 24 channels with 2 live accumulator pairs.
__global__ void __launch_bounds__(128, 3) bilat_kernel(
    const float* __restrict__ inp, const float* __restrict__ par,
    float* __restrict__ out)
{
    const int lane  = threadIdx.x & 31;
    const int ty    = threadIdx.x >> 5;
    const int tileX = blockIdx.x * 128;
    const int x0    = tileX + lane * 4;
    const int y     = blockIdx.y * 4 + ty;
    const int b     = blockIdx.z;

    const float* __restrict__ parb = par + b * (NP * HWSZ);
    const float* __restrict__ inpb = inp + b * (CIN * HWSZ);
    float* __restrict__ outb = out + b * (COUT * HWSZ);

    const int  xa  = max(x0 - 4, 0);        // lane-0 halo column (clamped)
    const int  xc  = min(x0 + 4, WW - 4);   // lane-31 halo column (clamped)
    const bool isL = (lane == 0);
    const bool isR = (lane == 31);

    int roff[5];
#pragma unroll
    for (int dy = 0; dy < 5; ++dy) {
        int ny = y + dy * 2 - 4;
        int nyc = min(max(ny, 0), HH - 1);
        roff[dy] = nyc * WW;
    }

    const int cbase = y * WW + x0;
    const u64 M1 = 0xBF800000BF800000ull;   // (-1.0f, -1.0f)

    // ---------------- Phase 1: squared param distances ----------------
    u64 d2[5][5][2];   // [dy][dx][pixel-pair] -> later reused as weights
#pragma unroll
    for (int dy = 0; dy < 5; ++dy)
#pragma unroll
        for (int dx = 0; dx < 5; ++dx) { d2[dy][dx][0] = 0ull; d2[dy][dx][1] = 0ull; }

#pragma unroll 1
    for (int p = 0; p < NP; ++p) {
        const float* pr = parb + p * HWSZ;
        ulonglong2 cc = __ldg(reinterpret_cast<const ulonglong2*>(pr + cbase));
#pragma unroll
        for (int dy = 0; dy < 5; ++dy) {
            ulonglong2 M = __ldg(reinterpret_cast<const ulonglong2*>(pr + roff[dy] + x0));
            u64 Lx = __shfl_up_sync(0xffffffffu, M.x, 1);
            u64 Ly = __shfl_up_sync(0xffffffffu, M.y, 1);
            u64 Rx = __shfl_down_sync(0xffffffffu, M.x, 1);
            u64 Ry = __shfl_down_sync(0xffffffffu, M.y, 1);
            if (isL) { ulonglong2 t = __ldg(reinterpret_cast<const ulonglong2*>(pr + roff[dy] + xa)); Lx = t.x; Ly = t.y; }
            if (isR) { ulonglong2 t = __ldg(reinterpret_cast<const ulonglong2*>(pr + roff[dy] + xc)); Rx = t.x; Ry = t.y; }
            u64 vp[6] = { Lx, Ly, M.x, M.y, Rx, Ry };
#pragma unroll
            for (int dx = 0; dx < 5; ++dx) {
                u64 t0 = fma2_(vp[dx],     M1, cc.x);
                u64 t1 = fma2_(vp[dx + 1], M1, cc.y);
                d2[dy][dx][0] = fma2_(t0, t0, d2[dy][dx][0]);
                d2[dy][dx][1] = fma2_(t1, t1, d2[dy][dx][1]);
            }
        }
    }

    // --------- Weights: exp(-d2), mask OOB taps, pre-normalize ---------
    u64 ws0 = 0ull, ws1 = 0ull;
#pragma unroll
    for (int dx = 0; dx < 5; ++dx) {
        const int g = x0 + dx * 2 - 4;      // global x of tap for pixel 0
        const float m0f = ((unsigned)(g + 0) < (unsigned)WW) ? 1.0f : 0.0f;
        const float m1f = ((unsigned)(g + 1) < (unsigned)WW) ? 1.0f : 0.0f;
        const float m2f = ((unsigned)(g + 2) < (unsigned)WW) ? 1.0f : 0.0f;
        const float m3f = ((unsigned)(g + 3) < (unsigned)WW) ? 1.0f : 0.0f;
        const u64 mxa = pack2_(m0f, m1f);
        const u64 mxb = pack2_(m2f, m3f);
#pragma unroll
        for (int dy = 0; dy < 5; ++dy) {
            const int ny = y + dy * 2 - 4;
            const float mr = ((unsigned)ny < (unsigned)HH) ? 1.0f : 0.0f;
            const u64 mrow = pack2_(mr, mr);
            float2 a = unpack2_(d2[dy][dx][0]);
            float2 c = unpack2_(d2[dy][dx][1]);
            u64 e0 = pack2_(__expf(-a.x), __expf(-a.y));
            u64 e1 = pack2_(__expf(-c.x), __expf(-c.y));
            e0 = mul2_(e0, mul2_(mxa, mrow));
            e1 = mul2_(e1, mul2_(mxb, mrow));
            d2[dy][dx][0] = e0;
            d2[dy][dx][1] = e1;
            ws0 = add2_(ws0, e0);
            ws1 = add2_(ws1, e1);
        }
    }
    {
        float2 s0 = unpack2_(ws0), s1 = unpack2_(ws1);
        const u64 r0 = pack2_(__fdividef(1.0f, s0.x + 1e-8f),
                              __fdividef(1.0f, s0.y + 1e-8f));
        const u64 r1 = pack2_(__fdividef(1.0f, s1.x + 1e-8f),
                              __fdividef(1.0f, s1.y + 1e-8f));
#pragma unroll
        for (int dy = 0; dy < 5; ++dy)
#pragma unroll
            for (int dx = 0; dx < 5; ++dx) {
                d2[dy][dx][0] = mul2_(d2[dy][dx][0], r0);
                d2[dy][dx][1] = mul2_(d2[dy][dx][1], r1);
            }
    }

    // ---------------- Phase 2: stream 24 channels ----------------
#pragma unroll 2
    for (int ch = 0; ch < COUT; ++ch) {
        const float* ir = inpb + ch * HWSZ;
        u64 a0 = 0ull, a1 = 0ull;
#pragma unroll
        for (int dy = 0; dy < 5; ++dy) {
            ulonglong2 M = __ldg(reinterpret_cast<const ulonglong2*>(ir + roff[dy] + x0));
            u64 Lx = __shfl_up_sync(0xffffffffu, M.x, 1);
            u64 Ly = __shfl_up_sync(0xffffffffu, M.y, 1);
            u64 Rx = __shfl_down_sync(0xffffffffu, M.x, 1);
            u64 Ry = __shfl_down_sync(0xffffffffu, M.y, 1);
            if (isL) { ulonglong2 t = __ldg(reinterpret_cast<const ulonglong2*>(ir + roff[dy] + xa)); Lx = t.x; Ly = t.y; }
            if (isR) { ulonglong2 t = __ldg(reinterpret_cast<const ulonglong2*>(ir + roff[dy] + xc)); Rx = t.x; Ry = t.y; }
            u64 vp[6] = { Lx, Ly, M.x, M.y, Rx, Ry };
#pragma unroll
            for (int dx = 0; dx < 5; ++dx) {
                a0 = fma2_(d2[dy][dx][0], vp[dx],     a0);
                a1 = fma2_(d2[dy][dx][1], vp[dx + 1], a1);
            }
        }
        float2 f0 = unpack2_(a0), f1 = unpack2_(a1);
        *reinterpret_cast<float4*>(outb + ch * HWSZ + cbase) =
            make_float4(f0.x, f0.y, f1.x, f1.y);
    }
}

extern "C" void kernel_launch(void* const* d_in, const int* in_sizes, int n_in,
                              void* d_out, int out_size)
{
    const float* inp = (const float*)d_in[0];   // (4,32,512,512) f32
    const float* par = (const float*)d_in[1];   // (4, 8,512,512) f32
    if (n_in >= 2 && in_sizes[0] < in_sizes[1]) {
        const float* t = inp; inp = par; par = t;
    }
    float* out = (float*)d_out;                 // (4,24,512,512) f32

    dim3 grid(WW / 128, HH / 4, 4);
    dim3 block(128);
    bilat_kernel<<<grid, block>>>(inp, par, out);
}

// round 3
// speedup vs baseline: 1.7240x; 1.7240x over previous
#include <cuda_runtime.h>

#define HH   512
#define WW   512
#define HWSZ (HH * WW)
#define CIN  32
#define COUT 24
#define NP   8

typedef unsigned long long u64;

// ---- B300 packed-f32 helpers (PTX f32x2 ops -> FFMA2 in SASS) ----
__device__ __forceinline__ u64 fma2_(u64 a, u64 b, u64 c) {
    u64 d; asm("fma.rn.f32x2 %0, %1, %2, %3;" : "=l"(d) : "l"(a), "l"(b), "l"(c)); return d;
}
__device__ __forceinline__ u64 add2_(u64 a, u64 b) {
    u64 d; asm("add.rn.f32x2 %0, %1, %2;" : "=l"(d) : "l"(a), "l"(b)); return d;
}
__device__ __forceinline__ u64 mul2_(u64 a, u64 b) {
    u64 d; asm("mul.rn.f32x2 %0, %1, %2;" : "=l"(d) : "l"(a), "l"(b)); return d;
}
__device__ __forceinline__ u64 pack2_(float lo, float hi) {
    u64 r; asm("mov.b64 %0, {%1, %2};" : "=l"(r) : "f"(lo), "f"(hi)); return r;
}
__device__ __forceinline__ float2 unpack2_(u64 v) {
    float lo, hi; asm("mov.b64 {%0, %1}, %2;" : "=f"(lo), "=f"(hi) : "l"(v));
    return make_float2(lo, hi);
}

// Thread = 4 x-adjacent pixels (x0 % 4 == 0). 12-float tap window
// [x0-4, x0+7] via 3 overlapping aligned LDG.128 (NO shuffles, NO divergent
// branches -- R2 proved those serialize the warp). Two phases:
//   1) build 25 pre-normalized weights (50 f32x2 pairs live in regs),
//   2) stream 24 channels with only 2 accumulator pairs live.
// 168 regs -> 3 CTAs/SM (12 warps) vs R1's 255 regs / 2 CTAs.
__global__ void __launch_bounds__(128, 3) bilat_kernel(
    const float* __restrict__ inp, const float* __restrict__ par,
    float* __restrict__ out)
{
    const int lane = threadIdx.x & 31;
    const int ty   = threadIdx.x >> 5;
    const int x0   = blockIdx.x * 128 + lane * 4;
    const int y    = blockIdx.y * 4 + ty;
    const int b    = blockIdx.z;

    const float* __restrict__ parb = par + b * (NP * HWSZ);
    const float* __restrict__ inpb = inp + b * (CIN * HWSZ);
    float* __restrict__ outb = out + b * (COUT * HWSZ);

    const int xa = max(x0 - 4, 0);          // clamped left column (16B aligned)
    const int xb = x0;
    const int xc = min(x0 + 4, WW - 4);     // clamped right column

    int roff[5];
#pragma unroll
    for (int dy = 0; dy < 5; ++dy) {
        int ny = y + dy * 2 - 4;
        roff[dy] = min(max(ny, 0), HH - 1) * WW;
    }

    const int cbase = y * WW + x0;
    const u64 M1 = 0xBF800000BF800000ull;   // (-1.0f, -1.0f)

    // ---------------- Phase 1: squared param distances ----------------
    u64 d2[5][5][2];   // [dy][dx][pixel-pair]; reused as normalized weights
#pragma unroll
    for (int dy = 0; dy < 5; ++dy)
#pragma unroll
        for (int dx = 0; dx < 5; ++dx) { d2[dy][dx][0] = 0ull; d2[dy][dx][1] = 0ull; }

#pragma unroll 1
    for (int p = 0; p < NP; ++p) {
        const float* pr = parb + p * HWSZ;
        ulonglong2 cc = __ldg(reinterpret_cast<const ulonglong2*>(pr + cbase));
#pragma unroll
        for (int dy = 0; dy < 5; ++dy) {
            ulonglong2 l0 = __ldg(reinterpret_cast<const ulonglong2*>(pr + roff[dy] + xa));
            ulonglong2 l1 = __ldg(reinterpret_cast<const ulonglong2*>(pr + roff[dy] + xb));
            ulonglong2 l2 = __ldg(reinterpret_cast<const ulonglong2*>(pr + roff[dy] + xc));
            u64 vp[6] = { l0.x, l0.y, l1.x, l1.y, l2.x, l2.y };
#pragma unroll
            for (int dx = 0; dx < 5; ++dx) {
                u64 t0 = fma2_(vp[dx],     M1, cc.x);   // neighbor - center
                u64 t1 = fma2_(vp[dx + 1], M1, cc.y);
                d2[dy][dx][0] = fma2_(t0, t0, d2[dy][dx][0]);
                d2[dy][dx][1] = fma2_(t1, t1, d2[dy][dx][1]);
            }
        }
    }

    // --------- Weights: exp(-d2), mask OOB taps (branch-free), normalize ---------
    u64 ws0 = 0ull, ws1 = 0ull;
#pragma unroll
    for (int dx = 0; dx < 5; ++dx) {
        const int g = x0 + dx * 2 - 4;      // global x of tap for pixel 0
        const u64 mxa = pack2_(((unsigned)(g + 0) < (unsigned)WW) ? 1.0f : 0.0f,
                               ((unsigned)(g + 1) < (unsigned)WW) ? 1.0f : 0.0f);
        const u64 mxb = pack2_(((unsigned)(g + 2) < (unsigned)WW) ? 1.0f : 0.0f,
                               ((unsigned)(g + 3) < (unsigned)WW) ? 1.0f : 0.0f);
#pragma unroll
        for (int dy = 0; dy < 5; ++dy) {
            const int ny = y + dy * 2 - 4;
            const float mr = ((unsigned)ny < (unsigned)HH) ? 1.0f : 0.0f;
            const u64 mrow = pack2_(mr, mr);
            float2 a = unpack2_(d2[dy][dx][0]);
            float2 c = unpack2_(d2[dy][dx][1]);
            u64 e0 = pack2_(__expf(-a.x), __expf(-a.y));
            u64 e1 = pack2_(__expf(-c.x), __expf(-c.y));
            e0 = mul2_(e0, mul2_(mxa, mrow));
            e1 = mul2_(e1, mul2_(mxb, mrow));
            d2[dy][dx][0] = e0;
            d2[dy][dx][1] = e1;
            ws0 = add2_(ws0, e0);
            ws1 = add2_(ws1, e1);
        }
    }
    {
        float2 s0 = unpack2_(ws0), s1 = unpack2_(ws1);
        const u64 r0 = pack2_(__fdividef(1.0f, s0.x + 1e-8f),
                              __fdividef(1.0f, s0.y + 1e-8f));
        const u64 r1 = pack2_(__fdividef(1.0f, s1.x + 1e-8f),
                              __fdividef(1.0f, s1.y + 1e-8f));
#pragma unroll
        for (int dy = 0; dy < 5; ++dy)
#pragma unroll
            for (int dx = 0; dx < 5; ++dx) {
                d2[dy][dx][0] = mul2_(d2[dy][dx][0], r0);
                d2[dy][dx][1] = mul2_(d2[dy][dx][1], r1);
            }
    }

    // ---------------- Phase 2: stream 24 channels ----------------
#pragma unroll 2
    for (int ch = 0; ch < COUT; ++ch) {
        const float* ir = inpb + ch * HWSZ;
        u64 a0 = 0ull, a1 = 0ull;
#pragma unroll
        for (int dy = 0; dy < 5; ++dy) {
            ulonglong2 l0 = __ldg(reinterpret_cast<const ulonglong2*>(ir + roff[dy] + xa));
            ulonglong2 l1 = __ldg(reinterpret_cast<const ulonglong2*>(ir + roff[dy] + xb));
            ulonglong2 l2 = __ldg(reinterpret_cast<const ulonglong2*>(ir + roff[dy] + xc));
            u64 vp[6] = { l0.x, l0.y, l1.x, l1.y, l2.x, l2.y };
#pragma unroll
            for (int dx = 0; dx < 5; ++dx) {
                a0 = fma2_(d2[dy][dx][0], vp[dx],     a0);
                a1 = fma2_(d2[dy][dx][1], vp[dx + 1], a1);
            }
        }
        float2 f0 = unpack2_(a0), f1 = unpack2_(a1);
        *reinterpret_cast<float4*>(outb + ch * HWSZ + cbase) =
            make_float4(f0.x, f0.y, f1.x, f1.y);
    }
}

extern "C" void kernel_launch(void* const* d_in, const int* in_sizes, int n_in,
                              void* d_out, int out_size)
{
    const float* inp = (const float*)d_in[0];   // (4,32,512,512) f32
    const float* par = (const float*)d_in[1];   // (4, 8,512,512) f32
    if (n_in >= 2 && in_sizes[0] < in_sizes[1]) {
        const float* t = inp; inp = par; par = t;
    }
    float* out = (float*)d_out;                 // (4,24,512,512) f32

    dim3 grid(WW / 128, HH / 4, 4);
    dim3 block(128);
    bilat_kernel<<<grid, block>>>(inp, par, out);
}

// round 4
// speedup vs baseline: 2.0157x; 1.1693x over previous
#include <cuda_runtime.h>

#define HH   512
#define WW   512
#define HWSZ (HH * WW)
#define CIN  32
#define COUT 24
#define NP   8

typedef unsigned long long u64;

// ---- B300 packed-f32 helpers (PTX f32x2 ops -> FFMA2 in SASS) ----
__device__ __forceinline__ u64 fma2_(u64 a, u64 b, u64 c) {
    u64 d; asm("fma.rn.f32x2 %0, %1, %2, %3;" : "=l"(d) : "l"(a), "l"(b), "l"(c)); return d;
}
__device__ __forceinline__ u64 add2_(u64 a, u64 b) {
    u64 d; asm("add.rn.f32x2 %0, %1, %2;" : "=l"(d) : "l"(a), "l"(b)); return d;
}
__device__ __forceinline__ u64 mul2_(u64 a, u64 b) {
    u64 d; asm("mul.rn.f32x2 %0, %1, %2;" : "=l"(d) : "l"(a), "l"(b)); return d;
}
__device__ __forceinline__ u64 pack2_(float lo, float hi) {
    u64 r; asm("mov.b64 %0, {%1, %2};" : "=l"(r) : "f"(lo), "f"(hi)); return r;
}
__device__ __forceinline__ float2 unpack2_(u64 v) {
    float lo, hi; asm("mov.b64 {%0, %1}, %2;" : "=f"(lo), "=f"(hi) : "l"(v));
    return make_float2(lo, hi);
}

// Thread = 4 x-adjacent pixels (x0 % 4 == 0); window [x0-4, x0+7] via 3
// overlapping aligned LDG.128 (no shuffles/divergence).
// Phase 1: dy-OUTER, fully unrolled -- each dy issues 32 independent loads
//          (8 params x {center + 3 rows}) in one flat block, then squares,
//          exps, masks -> 25 RAW weights kept in 50 reg pairs.
// Normalization folded into the final per-channel store (out = acc * rnorm).
// Phase 2: stream 24 channels, 2 live accumulator pairs, unroll 2.
__global__ void __launch_bounds__(128, 3) bilat_kernel(
    const float* __restrict__ inp, const float* __restrict__ par,
    float* __restrict__ out)
{
    const int lane = threadIdx.x & 31;
    const int ty   = threadIdx.x >> 5;
    const int x0   = blockIdx.x * 128 + lane * 4;
    const int y    = blockIdx.y * 4 + ty;
    const int b    = blockIdx.z;

    const float* __restrict__ parb = par + b * (NP * HWSZ);
    const float* __restrict__ inpb = inp + b * (CIN * HWSZ);
    float* __restrict__ outb = out + b * (COUT * HWSZ);

    const int xa = max(x0 - 4, 0);          // clamped left col (16B aligned)
    const int xb = x0;
    const int xc = min(x0 + 4, WW - 4);     // clamped right col

    int roff[5];
#pragma unroll
    for (int dy = 0; dy < 5; ++dy) {
        int ny = y + dy * 2 - 4;
        roff[dy] = min(max(ny, 0), HH - 1) * WW;
    }

    const int cbase = y * WW + x0;
    const u64 M1 = 0xBF800000BF800000ull;   // (-1.0f, -1.0f)

    u64 w[5][5][2];          // raw (unnormalized) weights
    u64 ws0 = 0ull, ws1 = 0ull;

    // ---------------- Phase 1: weights, dy-outer ----------------
#pragma unroll
    for (int dy = 0; dy < 5; ++dy) {
        u64 d2[5][2];
#pragma unroll
        for (int dx = 0; dx < 5; ++dx) { d2[dx][0] = 0ull; d2[dx][1] = 0ull; }

        const int ro = roff[dy];
#pragma unroll
        for (int p = 0; p < NP; ++p) {
            const float* pr = parb + p * HWSZ;
            ulonglong2 cc = __ldg(reinterpret_cast<const ulonglong2*>(pr + cbase));
            ulonglong2 l0 = __ldg(reinterpret_cast<const ulonglong2*>(pr + ro + xa));
            ulonglong2 l1 = __ldg(reinterpret_cast<const ulonglong2*>(pr + ro + xb));
            ulonglong2 l2 = __ldg(reinterpret_cast<const ulonglong2*>(pr + ro + xc));
            u64 vp[6] = { l0.x, l0.y, l1.x, l1.y, l2.x, l2.y };
#pragma unroll
            for (int dx = 0; dx < 5; ++dx) {
                u64 t0 = fma2_(vp[dx],     M1, cc.x);   // neighbor - center
                u64 t1 = fma2_(vp[dx + 1], M1, cc.y);
                d2[dx][0] = fma2_(t0, t0, d2[dx][0]);
                d2[dx][1] = fma2_(t1, t1, d2[dx][1]);
            }
        }

        const int   ny = y + dy * 2 - 4;
        const float mr = ((unsigned)ny < (unsigned)HH) ? 1.0f : 0.0f;
#pragma unroll
        for (int dx = 0; dx < 5; ++dx) {
            const int g = x0 + dx * 2 - 4;   // global x of tap for pixel 0
            const u64 mA = pack2_(((unsigned)(g + 0) < (unsigned)WW) ? mr : 0.0f,
                                  ((unsigned)(g + 1) < (unsigned)WW) ? mr : 0.0f);
            const u64 mB = pack2_(((unsigned)(g + 2) < (unsigned)WW) ? mr : 0.0f,
                                  ((unsigned)(g + 3) < (unsigned)WW) ? mr : 0.0f);
            float2 a = unpack2_(d2[dx][0]);
            float2 c = unpack2_(d2[dx][1]);
            u64 e0 = mul2_(pack2_(__expf(-a.x), __expf(-a.y)), mA);
            u64 e1 = mul2_(pack2_(__expf(-c.x), __expf(-c.y)), mB);
            w[dy][dx][0] = e0;
            w[dy][dx][1] = e1;
            ws0 = add2_(ws0, e0);
            ws1 = add2_(ws1, e1);
        }
    }

    // normalization factors (applied at the final store)
    float2 s0 = unpack2_(ws0), s1 = unpack2_(ws1);
    const u64 r0 = pack2_(__fdividef(1.0f, s0.x + 1e-8f),
                          __fdividef(1.0f, s0.y + 1e-8f));
    const u64 r1 = pack2_(__fdividef(1.0f, s1.x + 1e-8f),
                          __fdividef(1.0f, s1.y + 1e-8f));

    // ---------------- Phase 2: stream 24 channels ----------------
#pragma unroll 2
    for (int ch = 0; ch < COUT; ++ch) {
        const float* ir = inpb + ch * HWSZ;
        u64 a0 = 0ull, a1 = 0ull;
#pragma unroll
        for (int dy = 0; dy < 5; ++dy) {
            const int ro = roff[dy];
            ulonglong2 l0 = __ldg(reinterpret_cast<const ulonglong2*>(ir + ro + xa));
            ulonglong2 l1 = __ldg(reinterpret_cast<const ulonglong2*>(ir + ro + xb));
            ulonglong2 l2 = __ldg(reinterpret_cast<const ulonglong2*>(ir + ro + xc));
            u64 vp[6] = { l0.x, l0.y, l1.x, l1.y, l2.x, l2.y };
#pragma unroll
            for (int dx = 0; dx < 5; ++dx) {
                a0 = fma2_(w[dy][dx][0], vp[dx],     a0);
                a1 = fma2_(w[dy][dx][1], vp[dx + 1], a1);
            }
        }
        float2 f0 = unpack2_(mul2_(a0, r0));
        float2 f1 = unpack2_(mul2_(a1, r1));
        *reinterpret_cast<float4*>(outb + ch * HWSZ + cbase) =
            make_float4(f0.x, f0.y, f1.x, f1.y);
    }
}

extern "C" void kernel_launch(void* const* d_in, const int* in_sizes, int n_in,
                              void* d_out, int out_size)
{
    const float* inp = (const float*)d_in[0];   // (4,32,512,512) f32
    const float* par = (const float*)d_in[1];   // (4, 8,512,512) f32
    if (n_in >= 2 && in_sizes[0] < in_sizes[1]) {
        const float* t = inp; inp = par; par = t;
    }
    float* out = (float*)d_out;                 // (4,24,512,512) f32

    dim3 grid(WW / 128, HH / 4, 4);
    dim3 block(128);
    bilat_kernel<<<grid, block>>>(inp, par, out);
}